// round 11
// baseline (speedup 1.0000x reference)
#include <cuda_runtime.h>
#include <cstdint>

#define NCTA 128
#define NTHR 512
constexpr int B = 64, T = 1024, D = 256, H = 256;
constexpr int GROUPS = 8, P = 16, BG = 8, CPC = 16;

__device__ unsigned g_arr[GROUPS][8][32];       // monotonic CTA-arrival counters
__device__ unsigned g_gen2[GROUPS][8][16][32];  // per-CTA gen slots (128B apart)
__device__ unsigned g_abort = 0;
__device__ float g_hb[B * H];

__device__ __forceinline__ uint64_t packf2(float lo, float hi) {
    uint64_t d; asm("mov.b64 %0, {%1, %2};" : "=l"(d) : "f"(lo), "f"(hi)); return d;
}
__device__ __forceinline__ float2 unpackf2(uint64_t v) {
    float2 r; asm("mov.b64 {%0, %1}, %2;" : "=f"(r.x), "=f"(r.y) : "l"(v)); return r;
}
__device__ __forceinline__ uint64_t fma2(uint64_t a, uint64_t b, uint64_t c) {
    uint64_t d;
    asm("fma.rn.f32x2 %0, %1, %2, %3;" : "=l"(d) : "l"(a), "l"(b), "l"(c));
    return d;
}
__device__ __forceinline__ float sigmoid_fast(float x) {
    return __fdividef(1.0f, 1.0f + __expf(-x));
}
__device__ __forceinline__ float tanh_fast(float x) {
    float e = __expf(2.0f * x);
    return 1.0f - __fdividef(2.0f, e + 1.0f);
}

__global__ void __launch_bounds__(NTHR, 1) rgru_kernel(
    const float* __restrict__ x, const float* __restrict__ h0,
    const float* __restrict__ eps,
    const float* __restrict__ Wz, const float* __restrict__ bz,
    const float* __restrict__ Wr, const float* __restrict__ br,
    const float* __restrict__ Wtx, const float* __restrict__ btx,
    const float* __restrict__ Wth, const float* __restrict__ bth,
    const float* __restrict__ Wd, const float* __restrict__ bd,
    float* __restrict__ out)
{
    __shared__ unsigned swc[8];
    __shared__ unsigned sbs[8];

    const int tid = threadIdx.x, l = tid & 31, w = tid >> 5;
    const int g = blockIdx.x >> 4, p = blockIdx.x & 15;
    const int Jb = p * CPC, Bb = g * BG;
    const int j = Jb + w;

    if (tid < 8) {
        swc[tid] = 0u;
        sbs[tid] = *(volatile unsigned*)&g_gen2[g][tid][p][0];
    }
    __syncthreads();
    unsigned sbr[8];
#pragma unroll
    for (int i = 0; i < 8; i++) sbr[i] = sbs[i];

    // packed weights (once)
    uint64_t wz2[8], wr2[8], wu2[4], wv2[4], wm2[4], wlv2[4];
#pragma unroll
    for (int q = 0; q < 4; q++)
#pragma unroll
        for (int i = 0; i < 2; i++) {
            int k0 = 128 * q + 4 * l + 2 * i;
            wz2[2 * q + i] = packf2(Wz[k0 * H + j], Wz[(k0 + 1) * H + j]);
            wr2[2 * q + i] = packf2(Wr[k0 * H + j], Wr[(k0 + 1) * H + j]);
        }
#pragma unroll
    for (int q = 0; q < 2; q++)
#pragma unroll
        for (int i = 0; i < 2; i++) {
            int k0 = 128 * q + 4 * l + 2 * i;
            wu2[2 * q + i]  = packf2(Wtx[k0 * H + j], Wtx[(k0 + 1) * H + j]);
            wv2[2 * q + i]  = packf2(Wth[k0 * H + j], Wth[(k0 + 1) * H + j]);
            wm2[2 * q + i]  = packf2(Wd[k0 * 2 * H + j], Wd[(k0 + 1) * 2 * H + j]);
            wlv2[2 * q + i] = packf2(Wd[k0 * 2 * H + j + H], Wd[(k0 + 1) * 2 * H + j + H]);
        }
    const float bzj = bz[j], brj = br[j], btxj = btx[j], bthj = bth[j];
    const float bmj = bd[j], blj = bd[j + H];

    auto arrive = [&](int id, unsigned tgt) {
        __threadfence();
        unsigned lastw = 0;
        if (l == 0) {
            unsigned o = atomicAdd(&swc[id], 1u);
            lastw = (((o + 1u) & 15u) == 0u);
        }
        lastw = __shfl_sync(0xffffffffu, lastw, 0);
        if (lastw) {
            unsigned lastc = 0;
            if (l == 0) {
                unsigned go = atomicAdd(&g_arr[g][id][0], 1u);
                lastc = (((go + 1u) & 15u) == 0u);
            }
            lastc = __shfl_sync(0xffffffffu, lastc, 0);
            if (lastc) {
                __threadfence();
                if (l < 16) *(volatile unsigned*)&g_gen2[g][id][l][0] = tgt;
            }
        }
    };
    auto waitg = [&](int id, unsigned tgt) {
        volatile unsigned* pp = &g_gen2[g][id][p][0];
        if ((int)(*pp - tgt) < 0) {
            long long t0 = clock64();
            while ((int)(*pp - tgt) < 0) {
                if (*(volatile unsigned*)&g_abort) return;
                if (clock64() - t0 > 2000000000LL) { atomicExch(&g_abort, 1u); return; }
            }
        }
        __threadfence();
    };

    // phase 1 on a 2-batch sub-block
    auto phase1 = [&](int bbase, int t) {
        float fin = 0.f;
        const int pb = Bb + bbase + (l & 1);
        const float* hrow_t = (t == 0) ? (h0 + pb * H)
                                       : (out + ((size_t)pb * T + (t - 1)) * H);
        float hpsel = __ldcg(hrow_t + j);
#pragma unroll
        for (int bb = 0; bb < 2; bb++) {
            const int b = Bb + bbase + bb;
            const float* xrow = x + ((size_t)b * T + t) * D;
            const float* hrow = (t == 0) ? (h0 + b * H)
                                         : (out + ((size_t)b * T + (t - 1)) * H);
            float4 xv0 = __ldg((const float4*)xrow + l);
            float4 xv1 = __ldg((const float4*)xrow + 32 + l);
            float4 hv0 = __ldcg((const float4*)hrow + l);
            float4 hv1 = __ldcg((const float4*)hrow + 32 + l);
            uint64_t a2[8] = { packf2(xv0.x, xv0.y), packf2(xv0.z, xv0.w),
                               packf2(xv1.x, xv1.y), packf2(xv1.z, xv1.w),
                               packf2(hv0.x, hv0.y), packf2(hv0.z, hv0.w),
                               packf2(hv1.x, hv1.y), packf2(hv1.z, hv1.w) };
            uint64_t sz2 = 0, sr2 = 0, su2 = 0, sv2 = 0;
#pragma unroll
            for (int i = 0; i < 8; i++) {
                sz2 = fma2(wz2[i], a2[i], sz2);
                sr2 = fma2(wr2[i], a2[i], sr2);
            }
#pragma unroll
            for (int i = 0; i < 4; i++) {
                su2 = fma2(wu2[i], a2[i], su2);
                sv2 = fma2(wv2[i], a2[4 + i], sv2);
            }
            float2 f;
            f = unpackf2(sz2); float sz = f.x + f.y;
            f = unpackf2(sr2); float sr = f.x + f.y;
            f = unpackf2(su2); float su = f.x + f.y;
            f = unpackf2(sv2); float sv = f.x + f.y;
            const bool hi16 = (l & 16) != 0;
            float sA = hi16 ? sz : su;
            float rA = __shfl_xor_sync(0xffffffffu, sA, 16);
            float zu = hi16 ? (su + rA) : (sz + rA);
            float sB = hi16 ? sr : sv;
            float rB = __shfl_xor_sync(0xffffffffu, sB, 16);
            float rv = hi16 ? (sv + rB) : (sr + rB);
            const bool hi8 = (l & 8) != 0;
            float sC = hi8 ? zu : rv;
            float rC = __shfl_xor_sync(0xffffffffu, sC, 8);
            float myv = hi8 ? (rv + rC) : (zu + rC);
            myv += __shfl_xor_sync(0xffffffffu, myv, 4);
            myv += __shfl_xor_sync(0xffffffffu, myv, 2);
            myv += __shfl_xor_sync(0xffffffffu, myv, 1);
            fin = ((l & 7) == bb) ? myv : fin;
        }
        const int tb = l & 1;
        float zs = __shfl_sync(0xffffffffu, fin, tb);
        float rs = __shfl_sync(0xffffffffu, fin, tb + 8);
        float us = __shfl_sync(0xffffffffu, fin, tb + 16);
        float vs = __shfl_sync(0xffffffffu, fin, tb + 24);
        float z  = sigmoid_fast(zs + bzj);
        float r  = sigmoid_fast(rs + brj);
        float th = tanh_fast(us + btxj + r * (vs + bthj));
        float hbv = fmaf(z, hpsel - th, th);
        if (l < 2) g_hb[(Bb + bbase + tb) * H + j] = hbv;
    };

    // phase 2 on a 2-batch sub-block
    auto phase2 = [&](int bbase, int t) {
        float fin = 0.f;
#pragma unroll
        for (int bb = 0; bb < 2; bb++) {
            const float* hbrow = g_hb + (Bb + bbase + bb) * H;
            float4 q0 = __ldcg((const float4*)hbrow + l);
            float4 q1 = __ldcg((const float4*)hbrow + 32 + l);
            uint64_t h2[4] = { packf2(q0.x, q0.y), packf2(q0.z, q0.w),
                               packf2(q1.x, q1.y), packf2(q1.z, q1.w) };
            uint64_t sm2 = 0, sl2 = 0;
#pragma unroll
            for (int i = 0; i < 4; i++) {
                sm2 = fma2(wm2[i], h2[i], sm2);
                sl2 = fma2(wlv2[i], h2[i], sl2);
            }
            float2 f;
            f = unpackf2(sm2); float sm = f.x + f.y;
            f = unpackf2(sl2); float sl = f.x + f.y;
            const bool hi16 = (l & 16) != 0;
            float sA = hi16 ? sm : sl;
            float rA = __shfl_xor_sync(0xffffffffu, sA, 16);
            float mv = hi16 ? (sl + rA) : (sm + rA);
            mv += __shfl_xor_sync(0xffffffffu, mv, 8);
            mv += __shfl_xor_sync(0xffffffffu, mv, 4);
            mv += __shfl_xor_sync(0xffffffffu, mv, 2);
            mv += __shfl_xor_sync(0xffffffffu, mv, 1);
            fin = ((l & 15) == bb) ? mv : fin;
        }
        const int tb = l & 1;
        float ms = __shfl_sync(0xffffffffu, fin, tb);
        float ls = __shfl_sync(0xffffffffu, fin, tb + 16);
        float mean = fminf(fmaxf(ms + bmj, -1000.0f), 1000.0f);
        float lv   = fminf(fmaxf(ls + blj, -30.0f), 30.0f);
        float ep   = __ldg(eps + ((size_t)(Bb + bbase + tb) * T + t) * H + j);
        float s    = fmaf(__expf(0.5f * lv), ep, mean);
        if (l < 2) {
            int b = Bb + bbase + tb;
            out[((size_t)b * T + t) * H + j] = s;
            if (t == T - 1) out[(size_t)B * T * H + b * H + j] = s;
        }
    };

    // main loop: 4-deep sub-block pipeline, no block syncs
    for (int t = 0; t < T; t++) {
        const unsigned tp1 = (unsigned)(t + 1);
#pragma unroll
        for (int s = 0; s < 4; s++) {
            if (t > 0) waitg(4 + s, sbr[4 + s] + (unsigned)t);
            phase1(2 * s, t);
            arrive(s, sbr[s] + tp1);
        }
#pragma unroll
        for (int s = 0; s < 4; s++) {
            waitg(s, sbr[s] + tp1);
            phase2(2 * s, t);
            arrive(4 + s, sbr[4 + s] + tp1);
        }
    }
}

extern "C" void kernel_launch(void* const* d_in, const int* in_sizes, int n_in,
                              void* d_out, int out_size) {
    const float* x   = (const float*)d_in[0];
    const float* h0  = (const float*)d_in[1];
    const float* eps = (const float*)d_in[2];
    const float* Wz  = (const float*)d_in[3];
    const float* bz  = (const float*)d_in[4];
    const float* Wr  = (const float*)d_in[5];
    const float* br  = (const float*)d_in[6];
    const float* Wtx = (const float*)d_in[7];
    const float* btx = (const float*)d_in[8];
    const float* Wth = (const float*)d_in[9];
    const float* bth = (const float*)d_in[10];
    const float* Wd  = (const float*)d_in[11];
    const float* bd  = (const float*)d_in[12];
    float* out = (float*)d_out;

    rgru_kernel<<<NCTA, NTHR>>>(x, h0, eps, Wz, bz, Wr, br,
                                Wtx, btx, Wth, bth, Wd, bd, out);
}